// round 6
// baseline (speedup 1.0000x reference)
#include <cuda_runtime.h>
#include <cuda_bf16.h>
#include <cstdint>

// LinAminoToAtom via mma.sync bf16 3-term split (tcgen05 unavailable: harness
// PTX target is compute_103, no 'a' features).
// Per node: D[j, bv] = sum_k A[j,k] * B[bv,k], K = 192 = 3 planes of 64:
//   A = [Wh | Wl | Wh],  B = [Xh | Xh | Xl]  -> hh + lh + hl (ll ~2e-5 dropped)

#define NODES 512
#define BATCH 64
#define AMINO 64
#define ATOMN 32
#define RMAXJ 416
#define NBV   192              // 64 b * 3 v (N)
#define KTOT  192              // 3 planes * 64 (K)
#define LDAB  400              // smem row stride bytes (100 banks = 4 mod 32: ldmatrix conflict-free)
#define A_REGION 51200         // 128 * 400
#define B_REGION 76800         // 192 * 400
#define XS_STRIDE 196          // x fp32 staging row stride (floats); 64*196*4 = 50176 <= A_REGION
#define SMEM_DYN (A_REGION + B_REGION)

__constant__ int c_reslen[20] = {4,10,7,7,5,8,8,3,9,7,7,8,7,10,6,5,6,13,11,6};

__device__ int d_type[NODES];
__device__ int d_len[NODES];
__device__ int d_gbase[NODES];

// ---------- setup: dtype-robust type read + prefix of lens (validated R2-R4) ----
__global__ void setup_kernel(const void* __restrict__ tids_raw) {
    const int* s32 = (const int*)tids_raw;
    __shared__ int s[NODES];
    __shared__ int flag64;
    int n = threadIdx.x;
    if (n == 0) flag64 = 1;
    __syncthreads();
    if (n < 256) {
        int lo = s32[2 * n], hi = s32[2 * n + 1];
        if (hi != 0 || (unsigned)lo >= 20u) atomicAnd(&flag64, 0);
    }
    __syncthreads();
    int t = flag64 ? s32[2 * n] : s32[n];
    int l = c_reslen[t];
    d_type[n] = t;
    d_len[n]  = l;
    s[n] = l;
    __syncthreads();
    for (int off = 1; off < NODES; off <<= 1) {
        int v = (n >= off) ? s[n - off] : 0;
        __syncthreads();
        s[n] += v;
        __syncthreads();
    }
    d_gbase[n] = s[n] - l;
}

// ---------------- helpers ----------------
__device__ __forceinline__ uint32_t smem_u32(const void* p) {
    uint32_t a;
    asm("{ .reg .u64 t; cvta.to.shared.u64 t, %1; cvt.u32.u64 %0, t; }"
        : "=r"(a) : "l"(p));
    return a;
}
__device__ __forceinline__ void bf16_split(float f, uint16_t& hb, uint16_t& lb) {
    __nv_bfloat16 h = __float2bfloat16_rn(f);
    float l = f - __bfloat162float(h);
    __nv_bfloat16 g = __float2bfloat16_rn(l);
    hb = __bfloat16_as_ushort(h);
    lb = __bfloat16_as_ushort(g);
}
#define LDSM_X4(r, a) \
    asm volatile("ldmatrix.sync.aligned.m8n8.x4.shared.b16 {%0,%1,%2,%3}, [%4];" \
        : "=r"((r)[0]), "=r"((r)[1]), "=r"((r)[2]), "=r"((r)[3]) : "r"(a))
#define LDSM_X2T(r, a) \
    asm volatile("ldmatrix.sync.aligned.m8n8.x2.trans.shared.b16 {%0,%1}, [%2];" \
        : "=r"((r)[0]), "=r"((r)[1]) : "r"(a))
__device__ __forceinline__ void mma_bf16(float* c, const uint32_t* a, const uint32_t* b) {
    asm volatile(
        "mma.sync.aligned.m16n8k16.row.col.f32.bf16.bf16.f32 "
        "{%0,%1,%2,%3}, {%4,%5,%6,%7}, {%8,%9}, {%0,%1,%2,%3};"
        : "+f"(c[0]), "+f"(c[1]), "+f"(c[2]), "+f"(c[3])
        : "r"(a[0]), "r"(a[1]), "r"(a[2]), "r"(a[3]), "r"(b[0]), "r"(b[1]));
}

__global__ void __launch_bounds__(256, 1)
lin_amino_kernel(const float* __restrict__ x, const float* __restrict__ W,
                 float* __restrict__ out, int G) {
    extern __shared__ char smem[];
    char*  Ap  = smem;                 // A planes [128][KTOT] bf16, stride LDAB
    char*  Bp  = smem + A_REGION;      // B planes [KTOT][NBV] bf16, stride LDAB
    float* xsf = (float*)smem;         // fp32 x staging (overlaps A; dead before A used)

    const int tid  = threadIdx.x;
    const int warp = tid >> 5;
    const int lane = tid & 31;
    const int n    = blockIdx.x;
    const int t    = d_type[n];
    const int len  = d_len[n];
    const int gb   = d_gbase[n];
    const int ntiles = (len + 3) >> 2;
    const int jmax   = len * ATOMN;

    // ---- stage x[:, n] fp32 -> xs (coalesced float4) ----
    for (int f = tid; f < BATCH * 48; f += 256) {
        int b = f / 48, c4 = f % 48;
        float4 v = *reinterpret_cast<const float4*>(
            x + ((size_t)b * NODES + n) * 192 + c4 * 4);
        *reinterpret_cast<float4*>(xsf + b * XS_STRIDE + c4 * 4) = v;
    }
    __syncthreads();

    // ---- convert xs -> B planes: rows p*64+a, col bytes 6b+2v ----
    for (int i = tid; i < AMINO * BATCH; i += 256) {
        int a = i & 63, b = i >> 6;
        const float* s = xsf + b * XS_STRIDE + a * 3;
        uint16_t h0, l0, h1, l1, h2, l2;
        bf16_split(s[0], h0, l0);
        bf16_split(s[1], h1, l1);
        bf16_split(s[2], h2, l2);
        char* r0 = Bp + a * LDAB + b * 6;          // plane 0: Xh
        char* r1 = r0 + 64 * LDAB;                 // plane 1: Xh
        char* r2 = r0 + 128 * LDAB;                // plane 2: Xl
        *(uint16_t*)(r0 + 0) = h0; *(uint16_t*)(r0 + 2) = h1; *(uint16_t*)(r0 + 4) = h2;
        *(uint16_t*)(r1 + 0) = h0; *(uint16_t*)(r1 + 2) = h1; *(uint16_t*)(r1 + 4) = h2;
        *(uint16_t*)(r2 + 0) = l0; *(uint16_t*)(r2 + 2) = l1; *(uint16_t*)(r2 + 4) = l2;
    }
    __syncthreads();   // B ready; xs dead -> A region free

    const float* Wt = W + (size_t)t * AMINO * RMAXJ;
    const uint32_t sb    = smem_u32(smem);
    const uint32_t Abase = sb;
    const uint32_t Bbase = sb + A_REGION;

    const int m_block = (warp & 3) * 32;       // residue-local rows
    const int n_block = (warp >> 2) * 96;      // bv half
    const int l15 = lane & 15, lh = lane >> 4;
    const uint32_t aaddr0 = Abase + (uint32_t)(m_block + l15) * LDAB + lh * 16;
    const uint32_t aaddr1 = aaddr0 + 16 * LDAB;
    const uint32_t baddr0 = Bbase + (uint32_t)l15 * LDAB + n_block * 2;

    const int jw = tid & 127;        // staging: j row
    const int ah = tid >> 7;         // staging: amino half

    for (int mt = 0; mt < ntiles; ++mt) {
        if (mt) __syncthreads();     // prior tile's ldmatrix done before restage

        // ---- stage A planes [Wh | Wl | Wh] for rows jbase..+128 ----
        {
            int jg = mt * 128 + jw;
            bool val = jg < jmax;
            char* rowp = Ap + jw * LDAB;
#pragma unroll 8
            for (int aa = 0; aa < 32; ++aa) {
                int a = ah * 32 + aa;
                float w = val ? Wt[(size_t)a * RMAXJ + jg] : 0.0f;
                uint16_t hb, lb;
                bf16_split(w, hb, lb);
                *(uint16_t*)(rowp + a * 2)       = hb;   // plane 0: Wh
                *(uint16_t*)(rowp + 128 + a * 2) = lb;   // plane 1: Wl
                *(uint16_t*)(rowp + 256 + a * 2) = hb;   // plane 2: Wh
            }
        }
        __syncthreads();

        // ---- mainloop: 12 k-steps x (2 A-frags, 12 B-frags, 24 MMA) ----
        float acc[2][12][4];
#pragma unroll
        for (int i = 0; i < 2; ++i)
#pragma unroll
            for (int j = 0; j < 12; ++j)
#pragma unroll
                for (int k = 0; k < 4; ++k) acc[i][j][k] = 0.0f;

#pragma unroll 2
        for (int ks = 0; ks < 12; ++ks) {
            uint32_t a0[4], a1[4];
            LDSM_X4(a0, aaddr0 + ks * 32);
            LDSM_X4(a1, aaddr1 + ks * 32);
            uint32_t bk = baddr0 + (uint32_t)(ks * 16) * LDAB;
#pragma unroll
            for (int nf = 0; nf < 12; ++nf) {
                uint32_t bb[2];
                LDSM_X2T(bb, bk + nf * 16);
                mma_bf16(acc[0][nf], a0, bb);
                mma_bf16(acc[1][nf], a1, bb);
            }
        }

        // ---- epilogue: direct STG from D fragments ----
        {
            int r_idx = mt * 4 + (warp & 3);
            if (r_idx < len) {
                const size_t Gs = (size_t)G * 96;
                float* og = out + (size_t)(gb + r_idx) * 96;
                int row0 = lane >> 2, npair = (lane & 3) * 2;
#pragma unroll
                for (int mi = 0; mi < 2; ++mi) {
#pragma unroll
                    for (int nf = 0; nf < 12; ++nf) {
                        int n0 = n_block + nf * 8 + npair;
                        int b0 = n0 / 3, v0 = n0 - 3 * b0;
                        int n1 = n0 + 1;
                        int b1 = n1 / 3, v1 = n1 - 3 * b1;
                        int atomA = mi * 16 + row0;
                        int atomB = atomA + 8;
                        float* p0 = og + (size_t)b0 * Gs;
                        float* p1 = og + (size_t)b1 * Gs;
                        const float* c = acc[mi][nf];
                        p0[atomA * 3 + v0] = c[0];
                        p1[atomA * 3 + v1] = c[1];
                        p0[atomB * 3 + v0] = c[2];
                        p1[atomB * 3 + v1] = c[3];
                    }
                }
            }
        }
    }
}

extern "C" void kernel_launch(void* const* d_in, const int* in_sizes, int n_in,
                              void* d_out, int out_size) {
    const float* x    = (const float*)d_in[0];
    const float* W    = (const float*)d_in[1];
    const void*  tids = d_in[2];
    float*       out  = (float*)d_out;

    int G = in_sizes[3];

    cudaFuncSetAttribute(lin_amino_kernel,
                         cudaFuncAttributeMaxDynamicSharedMemorySize, SMEM_DYN);

    setup_kernel<<<1, NODES>>>(tids);
    lin_amino_kernel<<<NODES, 256, SMEM_DYN>>>(x, W, out, G);
}

// round 7
// speedup vs baseline: 1.2874x; 1.2874x over previous
#include <cuda_runtime.h>
#include <cuda_bf16.h>
#include <cstdint>

// LinAminoToAtom via mma.sync bf16 3-term split, deduped K planes + N-split blocks.
// Per node: D[j, bv] = sum_a W[a,j] * X[a,bv]; planes A=[Wh|Wl] (K=128),
// B=[Xh|Xl] (K=128); 12 k16-steps as (Wh,Xh)x4, (Wl,Xh)x4, (Wh,Xl)x4.
// Block = (node, batch-half): M=128 (4 residues x 32 atoms), N=96 (32 b x 3 v).

#define NODES 512
#define BATCH 64
#define AMINO 64
#define ATOMN 32
#define RMAXJ 416
#define LDA   272              // A smem row stride bytes (17*16, odd 16B units)
#define LDB   208              // B smem row stride bytes (13*16, odd 16B units)
#define A_REGION (128 * LDA)   // 34816
#define B_REGION (128 * LDB)   // 26624
#define XS_STRIDE 196          // x staging row stride (floats); 32*196*4=25088 < A_REGION
#define SMEM_DYN (A_REGION + B_REGION)

__constant__ int c_reslen[20] = {4,10,7,7,5,8,8,3,9,7,7,8,7,10,6,5,6,13,11,6};

__device__ int d_type[NODES];
__device__ int d_len[NODES];
__device__ int d_gbase[NODES];

// ---------- setup: dtype-robust type read + prefix of lens (validated) ----------
__global__ void setup_kernel(const void* __restrict__ tids_raw) {
    const int* s32 = (const int*)tids_raw;
    __shared__ int s[NODES];
    __shared__ int flag64;
    int n = threadIdx.x;
    if (n == 0) flag64 = 1;
    __syncthreads();
    if (n < 256) {
        int lo = s32[2 * n], hi = s32[2 * n + 1];
        if (hi != 0 || (unsigned)lo >= 20u) atomicAnd(&flag64, 0);
    }
    __syncthreads();
    int t = flag64 ? s32[2 * n] : s32[n];
    int l = c_reslen[t];
    d_type[n] = t;
    d_len[n]  = l;
    s[n] = l;
    __syncthreads();
    for (int off = 1; off < NODES; off <<= 1) {
        int v = (n >= off) ? s[n - off] : 0;
        __syncthreads();
        s[n] += v;
        __syncthreads();
    }
    d_gbase[n] = s[n] - l;
}

// ---------------- helpers ----------------
__device__ __forceinline__ uint32_t smem_u32(const void* p) {
    uint32_t a;
    asm("{ .reg .u64 t; cvta.to.shared.u64 t, %1; cvt.u32.u64 %0, t; }"
        : "=r"(a) : "l"(p));
    return a;
}
__device__ __forceinline__ void bf16_split(float f, uint16_t& hb, uint16_t& lb) {
    __nv_bfloat16 h = __float2bfloat16_rn(f);
    float l = f - __bfloat162float(h);
    __nv_bfloat16 g = __float2bfloat16_rn(l);
    hb = __bfloat16_as_ushort(h);
    lb = __bfloat16_as_ushort(g);
}
#define LDSM_X4(r, a) \
    asm volatile("ldmatrix.sync.aligned.m8n8.x4.shared.b16 {%0,%1,%2,%3}, [%4];" \
        : "=r"((r)[0]), "=r"((r)[1]), "=r"((r)[2]), "=r"((r)[3]) : "r"(a))
#define LDSM_X2T(r, a) \
    asm volatile("ldmatrix.sync.aligned.m8n8.x2.trans.shared.b16 {%0,%1}, [%2];" \
        : "=r"((r)[0]), "=r"((r)[1]) : "r"(a))
__device__ __forceinline__ void mma_bf16(float* c, const uint32_t* a, const uint32_t* b) {
    asm volatile(
        "mma.sync.aligned.m16n8k16.row.col.f32.bf16.bf16.f32 "
        "{%0,%1,%2,%3}, {%4,%5,%6,%7}, {%8,%9}, {%0,%1,%2,%3};"
        : "+f"(c[0]), "+f"(c[1]), "+f"(c[2]), "+f"(c[3])
        : "r"(a[0]), "r"(a[1]), "r"(a[2]), "r"(a[3]), "r"(b[0]), "r"(b[1]));
}

__global__ void __launch_bounds__(256, 2)
lin_amino_kernel(const float* __restrict__ x, const float* __restrict__ W,
                 float* __restrict__ out, int G) {
    extern __shared__ char smem[];
    char*  Ap  = smem;                 // A: [128 j][LDA] = [Wh(128B) | Wl(128B)]
    char*  Bp  = smem + A_REGION;      // B: [128 k][LDB]; rows 0-63 Xh, 64-127 Xl
    float* xsf = (float*)smem;         // fp32 x staging (32 batches, overlaps A)

    const int tid  = threadIdx.x;
    const int warp = tid >> 5;
    const int lane = tid & 31;
    const int bx   = blockIdx.x;
    const int n    = bx >> 1;
    const int half = bx & 1;           // batch half: b in [32*half, 32*half+32)
    const int t    = d_type[n];
    const int len  = d_len[n];
    const int gb   = d_gbase[n];
    const int ntiles = (len + 3) >> 2;
    const int jmax   = len * ATOMN;

    // ---- stage x[b0..b0+32, n] fp32 -> xs (coalesced float4) ----
    for (int f = tid; f < 32 * 48; f += 256) {
        int b = f / 48, c4 = f % 48;
        float4 v = *reinterpret_cast<const float4*>(
            x + ((size_t)(half * 32 + b) * NODES + n) * 192 + c4 * 4);
        *reinterpret_cast<float4*>(xsf + b * XS_STRIDE + c4 * 4) = v;
    }
    __syncthreads();

    // ---- convert xs -> B planes: row a (Xh) / 64+a (Xl), col bytes 6*bl+2*v ----
    for (int i = tid; i < AMINO * 32; i += 256) {
        int a = i & 63, bl = i >> 6;
        const float* s = xsf + bl * XS_STRIDE + a * 3;
        uint16_t h0, l0, h1, l1, h2, l2;
        bf16_split(s[0], h0, l0);
        bf16_split(s[1], h1, l1);
        bf16_split(s[2], h2, l2);
        char* rh = Bp + a * LDB + bl * 6;
        char* rl = rh + 64 * LDB;
        *(uint16_t*)(rh + 0) = h0; *(uint16_t*)(rh + 2) = h1; *(uint16_t*)(rh + 4) = h2;
        *(uint16_t*)(rl + 0) = l0; *(uint16_t*)(rl + 2) = l1; *(uint16_t*)(rl + 4) = l2;
    }
    __syncthreads();   // B ready; xs dead -> A region free

    const float* Wt = W + (size_t)t * AMINO * RMAXJ;
    const uint32_t Abase = smem_u32(smem);
    const uint32_t Bbase = Abase + A_REGION;

    const int m_block = (warp & 3) * 32;    // residue-local rows (warp&3 = residue)
    const int n_block = (warp >> 2) * 48;   // 6 n-frags of 8
    const int l15 = lane & 15, lh = lane >> 4;
    const uint32_t aaddr0 = Abase + (uint32_t)(m_block + l15) * LDA + lh * 16;
    const uint32_t aaddr1 = aaddr0 + 16 * LDA;
    const uint32_t bbase_lane = Bbase + (uint32_t)l15 * LDB + n_block * 2;

    const int jw = tid & 127;      // A staging: j row
    const int ah = tid >> 7;       // A staging: amino half (32 a's)

    for (int mt = 0; mt < ntiles; ++mt) {
        if (mt) __syncthreads();   // prior ldmatrix done before restage

        // ---- stage A: rows jbase..+128, [Wh | Wl], vectorized u4 stores ----
        {
            int jg = mt * 128 + jw;
            bool val = jg < jmax;
            uint32_t hp[16], lp[16];
#pragma unroll 4
            for (int q = 0; q < 16; ++q) {
                int a = ah * 32 + 2 * q;
                float w0 = val ? Wt[(size_t)a * RMAXJ + jg] : 0.0f;
                float w1 = val ? Wt[(size_t)(a + 1) * RMAXJ + jg] : 0.0f;
                uint16_t hb0, lb0, hb1, lb1;
                bf16_split(w0, hb0, lb0);
                bf16_split(w1, hb1, lb1);
                hp[q] = (uint32_t)hb0 | ((uint32_t)hb1 << 16);
                lp[q] = (uint32_t)lb0 | ((uint32_t)lb1 << 16);
            }
            char* rowp = Ap + jw * LDA + ah * 64;
#pragma unroll
            for (int q4 = 0; q4 < 4; ++q4) {
                *reinterpret_cast<uint4*>(rowp + q4 * 16) =
                    make_uint4(hp[4*q4], hp[4*q4+1], hp[4*q4+2], hp[4*q4+3]);
                *reinterpret_cast<uint4*>(rowp + 128 + q4 * 16) =
                    make_uint4(lp[4*q4], lp[4*q4+1], lp[4*q4+2], lp[4*q4+3]);
            }
        }
        __syncthreads();

        // ---- mainloop: 12 k-steps = (Wh,Xh)x4, (Wl,Xh)x4, (Wh,Xl)x4 ----
        float acc[2][6][4];
#pragma unroll
        for (int i = 0; i < 2; ++i)
#pragma unroll
            for (int j = 0; j < 6; ++j)
#pragma unroll
                for (int k = 0; k < 4; ++k) acc[i][j][k] = 0.0f;

#pragma unroll
        for (int s = 0; s < 12; ++s) {
            int quad = s >> 2, kk = s & 3;
            int pa = (quad == 1);          // Wl on quad 1
            int pb = (quad == 2);          // Xl on quad 2
            uint32_t a0[4], a1[4];
            uint32_t aoff = (uint32_t)(pa * 128 + kk * 32);
            LDSM_X4(a0, aaddr0 + aoff);
            LDSM_X4(a1, aaddr1 + aoff);
            uint32_t bk = bbase_lane + (uint32_t)(pb * 64 + kk * 16) * LDB;
#pragma unroll
            for (int nf = 0; nf < 6; ++nf) {
                uint32_t bb[2];
                LDSM_X2T(bb, bk + nf * 16);
                mma_bf16(acc[0][nf], a0, bb);
                mma_bf16(acc[1][nf], a1, bb);
            }
        }

        // ---- epilogue: direct STG from D fragments ----
        {
            int r_idx = mt * 4 + (warp & 3);
            if (r_idx < len) {
                const size_t Gs = (size_t)G * 96;
                float* og = out + (size_t)(gb + r_idx) * 96 + (size_t)(half * 32) * Gs;
                int row0 = lane >> 2, npair = (lane & 3) * 2;
#pragma unroll
                for (int mi = 0; mi < 2; ++mi) {
#pragma unroll
                    for (int nf = 0; nf < 6; ++nf) {
                        int n0 = n_block + nf * 8 + npair;
                        int b0 = n0 / 3, v0 = n0 - 3 * b0;
                        int n1 = n0 + 1;
                        int b1 = n1 / 3, v1 = n1 - 3 * b1;
                        int atomA = mi * 16 + row0;
                        int atomB = atomA + 8;
                        float* p0 = og + (size_t)b0 * Gs;
                        float* p1 = og + (size_t)b1 * Gs;
                        const float* c = acc[mi][nf];
                        p0[atomA * 3 + v0] = c[0];
                        p1[atomA * 3 + v1] = c[1];
                        p0[atomB * 3 + v0] = c[2];
                        p1[atomB * 3 + v1] = c[3];
                    }
                }
            }
        }
    }
}

extern "C" void kernel_launch(void* const* d_in, const int* in_sizes, int n_in,
                              void* d_out, int out_size) {
    const float* x    = (const float*)d_in[0];
    const float* W    = (const float*)d_in[1];
    const void*  tids = d_in[2];
    float*       out  = (float*)d_out;

    int G = in_sizes[3];

    cudaFuncSetAttribute(lin_amino_kernel,
                         cudaFuncAttributeMaxDynamicSharedMemorySize, SMEM_DYN);

    setup_kernel<<<1, NODES>>>(tids);
    lin_amino_kernel<<<NODES * 2, 256, SMEM_DYN>>>(x, W, out, G);
}

// round 8
// speedup vs baseline: 1.3964x; 1.0847x over previous
#include <cuda_runtime.h>
#include <cuda_bf16.h>
#include <cstdint>

// LinAminoToAtom via mma.sync bf16 3-term split.
// R8: precompute Wh/Wl and Xh/Xl tile IMAGES (exact smem byte layout) once per
// launch into __device__ scratch; hot kernel stages via cp.async only
// (double-buffered A), mainloop/epilogue identical to validated R7.

#define NODES 512
#define BATCH 64
#define AMINO 64
#define ATOMN 32
#define RMAXJ 416
#define LDA   272              // A smem row stride bytes
#define LDB   208              // B smem row stride bytes
#define A_REGION (128 * LDA)   // 34816
#define B_REGION (128 * LDB)   // 26624
#define A_V4  (A_REGION / 16)  // 2176
#define B_V4  (B_REGION / 16)  // 1664
#define XS_STRIDE 196          // x staging row stride (floats)

__constant__ int c_reslen[20] = {4,10,7,7,5,8,8,3,9,7,7,8,7,10,6,5,6,13,11,6};

__device__ int d_type[NODES];
__device__ int d_len[NODES];
__device__ int d_gbase[NODES];
__device__ uint4 d_Wprep[20 * 4 * A_V4];      // 2.79 MB : per (type, mtile) A image
__device__ uint4 d_Xprep[NODES * 2 * B_V4];   // 27.3 MB : per (node, half) B image

// ---------- setup (validated R2-R7): dtype-robust types + prefix of lens ------
__global__ void setup_kernel(const void* __restrict__ tids_raw) {
    const int* s32 = (const int*)tids_raw;
    __shared__ int s[NODES];
    __shared__ int flag64;
    int n = threadIdx.x;
    if (n == 0) flag64 = 1;
    __syncthreads();
    if (n < 256) {
        int lo = s32[2 * n], hi = s32[2 * n + 1];
        if (hi != 0 || (unsigned)lo >= 20u) atomicAnd(&flag64, 0);
    }
    __syncthreads();
    int t = flag64 ? s32[2 * n] : s32[n];
    int l = c_reslen[t];
    d_type[n] = t;
    d_len[n]  = l;
    s[n] = l;
    __syncthreads();
    for (int off = 1; off < NODES; off <<= 1) {
        int v = (n >= off) ? s[n - off] : 0;
        __syncthreads();
        s[n] += v;
        __syncthreads();
    }
    d_gbase[n] = s[n] - l;
}

// ---------------- helpers ----------------
__device__ __forceinline__ uint32_t smem_u32(const void* p) {
    uint32_t a;
    asm("{ .reg .u64 t; cvta.to.shared.u64 t, %1; cvt.u32.u64 %0, t; }"
        : "=r"(a) : "l"(p));
    return a;
}
__device__ __forceinline__ void bf16_split(float f, uint16_t& hb, uint16_t& lb) {
    __nv_bfloat16 h = __float2bfloat16_rn(f);
    float l = f - __bfloat162float(h);
    __nv_bfloat16 g = __float2bfloat16_rn(l);
    hb = __bfloat16_as_ushort(h);
    lb = __bfloat16_as_ushort(g);
}
#define LDSM_X4(r, a) \
    asm volatile("ldmatrix.sync.aligned.m8n8.x4.shared.b16 {%0,%1,%2,%3}, [%4];" \
        : "=r"((r)[0]), "=r"((r)[1]), "=r"((r)[2]), "=r"((r)[3]) : "r"(a))
#define LDSM_X2T(r, a) \
    asm volatile("ldmatrix.sync.aligned.m8n8.x2.trans.shared.b16 {%0,%1}, [%2];" \
        : "=r"((r)[0]), "=r"((r)[1]) : "r"(a))
__device__ __forceinline__ void mma_bf16(float* c, const uint32_t* a, const uint32_t* b) {
    asm volatile(
        "mma.sync.aligned.m16n8k16.row.col.f32.bf16.bf16.f32 "
        "{%0,%1,%2,%3}, {%4,%5,%6,%7}, {%8,%9}, {%0,%1,%2,%3};"
        : "+f"(c[0]), "+f"(c[1]), "+f"(c[2]), "+f"(c[3])
        : "r"(a[0]), "r"(a[1]), "r"(a[2]), "r"(a[3]), "r"(b[0]), "r"(b[1]));
}
#define CP_ASYNC16(dst, src) \
    asm volatile("cp.async.cg.shared.global [%0], [%1], 16;" :: "r"(dst), "l"(src))
#define CP_COMMIT() asm volatile("cp.async.commit_group;" ::: "memory")
#define CP_WAIT0()  asm volatile("cp.async.wait_group 0;" ::: "memory")

// ---------- prep_w: A image per (type, mtile): [128 j][Wh(2x64B)|Wl] ----------
__global__ void prep_w_kernel(const float* __restrict__ W) {
    __shared__ char Aimg[A_REGION];
    const int t  = blockIdx.x >> 2;
    const int mt = blockIdx.x & 3;
    const int tid = threadIdx.x;
    const int jw = tid & 127, ah = tid >> 7;
    const int jmax = c_reslen[t] * ATOMN;
    const float* Wt = W + (size_t)t * AMINO * RMAXJ;
    {
        int jg = mt * 128 + jw;
        bool val = jg < jmax;
        uint32_t hp[16], lp[16];
#pragma unroll 4
        for (int q = 0; q < 16; ++q) {
            int a = ah * 32 + 2 * q;
            float w0 = val ? Wt[(size_t)a * RMAXJ + jg] : 0.0f;
            float w1 = val ? Wt[(size_t)(a + 1) * RMAXJ + jg] : 0.0f;
            uint16_t hb0, lb0, hb1, lb1;
            bf16_split(w0, hb0, lb0);
            bf16_split(w1, hb1, lb1);
            hp[q] = (uint32_t)hb0 | ((uint32_t)hb1 << 16);
            lp[q] = (uint32_t)lb0 | ((uint32_t)lb1 << 16);
        }
        char* rowp = Aimg + jw * LDA + ah * 64;
#pragma unroll
        for (int q4 = 0; q4 < 4; ++q4) {
            *reinterpret_cast<uint4*>(rowp + q4 * 16) =
                make_uint4(hp[4*q4], hp[4*q4+1], hp[4*q4+2], hp[4*q4+3]);
            *reinterpret_cast<uint4*>(rowp + 128 + q4 * 16) =
                make_uint4(lp[4*q4], lp[4*q4+1], lp[4*q4+2], lp[4*q4+3]);
        }
    }
    __syncthreads();
    uint4* dst = d_Wprep + (size_t)blockIdx.x * A_V4;
    const uint4* src = (const uint4*)Aimg;
    for (int i = tid; i < A_V4; i += 256) dst[i] = src[i];
}

// ---------- prep_x: B image per (node, half): rows a=Xh / 64+a=Xl -------------
__global__ void prep_x_kernel(const float* __restrict__ x) {
    extern __shared__ char psm[];
    float* xsf = (float*)psm;                       // 32*XS_STRIDE*4 = 25088
    char*  Bimg = psm + 32 * XS_STRIDE * 4;         // 26624
    const int bx = blockIdx.x;
    const int n = bx >> 1, half = bx & 1;
    const int tid = threadIdx.x;

    for (int f = tid; f < 32 * 48; f += 256) {
        int b = f / 48, c4 = f % 48;
        float4 v = *reinterpret_cast<const float4*>(
            x + ((size_t)(half * 32 + b) * NODES + n) * 192 + c4 * 4);
        *reinterpret_cast<float4*>(xsf + b * XS_STRIDE + c4 * 4) = v;
    }
    __syncthreads();
    for (int i = tid; i < AMINO * 32; i += 256) {
        int a = i & 63, bl = i >> 6;
        const float* s = xsf + bl * XS_STRIDE + a * 3;
        uint16_t h0, l0, h1, l1, h2, l2;
        bf16_split(s[0], h0, l0);
        bf16_split(s[1], h1, l1);
        bf16_split(s[2], h2, l2);
        char* rh = Bimg + a * LDB + bl * 6;
        char* rl = rh + 64 * LDB;
        *(uint16_t*)(rh + 0) = h0; *(uint16_t*)(rh + 2) = h1; *(uint16_t*)(rh + 4) = h2;
        *(uint16_t*)(rl + 0) = l0; *(uint16_t*)(rl + 2) = l1; *(uint16_t*)(rl + 4) = l2;
    }
    __syncthreads();
    uint4* dst = d_Xprep + (size_t)bx * B_V4;
    const uint4* src = (const uint4*)Bimg;
    for (int i = tid; i < B_V4; i += 256) dst[i] = src[i];
}

// ---------- main: cp.async staged, double-buffered A, R7 mainloop/epilogue ----
#define SMEM_MAIN (2 * A_REGION + B_REGION)   // 96256

__global__ void __launch_bounds__(256, 2)
lin_amino_kernel(float* __restrict__ out, int G) {
    extern __shared__ char smem[];
    const int tid  = threadIdx.x;
    const int warp = tid >> 5;
    const int lane = tid & 31;
    const int bx   = blockIdx.x;
    const int n    = bx >> 1;
    const int half = bx & 1;
    const int t    = d_type[n];
    const int len  = d_len[n];
    const int gb   = d_gbase[n];
    const int ntiles = (len + 3) >> 2;

    const uint32_t Abase = smem_u32(smem);
    const uint32_t Bsm   = Abase + 2 * A_REGION;

    // ---- initial fill: B image + A tile 0 ----
    {
        const char* bsrc = (const char*)(d_Xprep + (size_t)bx * B_V4);
        for (int i = tid; i < B_V4; i += 256)
            CP_ASYNC16(Bsm + i * 16, bsrc + i * 16);
        const char* asrc = (const char*)(d_Wprep + (size_t)(t * 4) * A_V4);
        for (int i = tid; i < A_V4; i += 256)
            CP_ASYNC16(Abase + i * 16, asrc + i * 16);
        CP_COMMIT();
    }

    const int m_block = (warp & 3) * 32;    // warp&3 = residue in tile
    const int n_block = (warp >> 2) * 48;   // 6 n-frags of 8
    const int l15 = lane & 15, lh = lane >> 4;
    const uint32_t aoff_lane = (uint32_t)(m_block + l15) * LDA + lh * 16;
    const uint32_t bbase_lane = Bsm + (uint32_t)l15 * LDB + n_block * 2;

    for (int mt = 0; mt < ntiles; ++mt) {
        CP_WAIT0();
        __syncthreads();
        const uint32_t Acur = Abase + (uint32_t)(mt & 1) * A_REGION;
        const uint32_t aaddr0 = Acur + aoff_lane;
        const uint32_t aaddr1 = aaddr0 + 16 * LDA;

        // ---- mainloop: 12 k-steps = (Wh,Xh)x4, (Wl,Xh)x4, (Wh,Xl)x4 ----
        float acc[2][6][4];
#pragma unroll
        for (int i = 0; i < 2; ++i)
#pragma unroll
            for (int j = 0; j < 6; ++j)
#pragma unroll
                for (int k = 0; k < 4; ++k) acc[i][j][k] = 0.0f;

#pragma unroll
        for (int s = 0; s < 12; ++s) {
            int quad = s >> 2, kk = s & 3;
            int pa = (quad == 1);
            int pb = (quad == 2);
            uint32_t a0[4], a1[4];
            uint32_t aoff = (uint32_t)(pa * 128 + kk * 32);
            LDSM_X4(a0, aaddr0 + aoff);
            LDSM_X4(a1, aaddr1 + aoff);
            uint32_t bk = bbase_lane + (uint32_t)(pb * 64 + kk * 16) * LDB;
#pragma unroll
            for (int nf = 0; nf < 6; ++nf) {
                uint32_t bb[2];
                LDSM_X2T(bb, bk + nf * 16);
                mma_bf16(acc[0][nf], a0, bb);
                mma_bf16(acc[1][nf], a1, bb);
            }
        }

        // ---- prefetch next A tile into alternate buffer (overlaps epilogue) --
        if (mt + 1 < ntiles) {
            const uint32_t Anext = Abase + (uint32_t)((mt + 1) & 1) * A_REGION;
            const char* asrc = (const char*)(d_Wprep + (size_t)(t * 4 + mt + 1) * A_V4);
            for (int i = tid; i < A_V4; i += 256)
                CP_ASYNC16(Anext + i * 16, asrc + i * 16);
            CP_COMMIT();
        }

        // ---- epilogue: direct STG from D fragments (validated R7) ----
        {
            int r_idx = mt * 4 + (warp & 3);
            if (r_idx < len) {
                const size_t Gs = (size_t)G * 96;
                float* og = out + (size_t)(gb + r_idx) * 96 + (size_t)(half * 32) * Gs;
                int row0 = lane >> 2, npair = (lane & 3) * 2;
#pragma unroll
                for (int mi = 0; mi < 2; ++mi) {
#pragma unroll
                    for (int nf = 0; nf < 6; ++nf) {
                        int n0 = n_block + nf * 8 + npair;
                        int b0 = n0 / 3, v0 = n0 - 3 * b0;
                        int n1 = n0 + 1;
                        int b1 = n1 / 3, v1 = n1 - 3 * b1;
                        int atomA = mi * 16 + row0;
                        int atomB = atomA + 8;
                        float* p0 = og + (size_t)b0 * Gs;
                        float* p1 = og + (size_t)b1 * Gs;
                        const float* c = acc[mi][nf];
                        p0[atomA * 3 + v0] = c[0];
                        p1[atomA * 3 + v1] = c[1];
                        p0[atomB * 3 + v0] = c[2];
                        p1[atomB * 3 + v1] = c[3];
                    }
                }
            }
        }
    }
}

extern "C" void kernel_launch(void* const* d_in, const int* in_sizes, int n_in,
                              void* d_out, int out_size) {
    const float* x    = (const float*)d_in[0];
    const float* W    = (const float*)d_in[1];
    const void*  tids = d_in[2];
    float*       out  = (float*)d_out;

    int G = in_sizes[3];

    cudaFuncSetAttribute(lin_amino_kernel,
                         cudaFuncAttributeMaxDynamicSharedMemorySize, SMEM_MAIN);
    cudaFuncSetAttribute(prep_x_kernel,
                         cudaFuncAttributeMaxDynamicSharedMemorySize,
                         32 * XS_STRIDE * 4 + B_REGION);

    setup_kernel<<<1, NODES>>>(tids);
    prep_w_kernel<<<80, 256>>>(W);
    prep_x_kernel<<<NODES * 2, 256, 32 * XS_STRIDE * 4 + B_REGION>>>(x);
    lin_amino_kernel<<<NODES * 2, 256, SMEM_MAIN>>>(out, G);
}

// round 9
// speedup vs baseline: 1.6520x; 1.1831x over previous
#include <cuda_runtime.h>
#include <cuda_bf16.h>
#include <cstdint>

// LinAminoToAtom via mma.sync bf16 3-term split.
// R9: prep_x fused into main prologue (direct LDG + split -> B smem);
// M-tile = 64 rows (2 residues) -> smem 61.4KB -> 3 CTAs/SM.
// Planes: A=[Wh|Wl] (K=128 bytes dedup), B=[Xh|Xl]; 12 k16-steps =
// (Wh,Xh)x4, (Wl,Xh)x4, (Wh,Xl)x4  (ll term dropped, ~4.4e-6).

#define NODES 512
#define BATCH 64
#define AMINO 64
#define ATOMN 32
#define RMAXJ 416
#define LDA   272              // A smem row stride bytes
#define LDB   208              // B smem row stride bytes
#define A_ROWS 64              // M-tile rows
#define A_REGION (A_ROWS * LDA)   // 17408
#define B_REGION (128 * LDB)      // 26624
#define A_V4  (A_REGION / 16)     // 1088
#define NTILE_MAX 7               // ceil(13*32/64)

__constant__ int c_reslen[20] = {4,10,7,7,5,8,8,3,9,7,7,8,7,10,6,5,6,13,11,6};

__device__ int d_type[NODES];
__device__ int d_len[NODES];
__device__ int d_gbase[NODES];
__device__ uint4 d_Wprep[20 * NTILE_MAX * A_V4];   // 2.44 MB per-(type,mtile) A image

// ---------- setup (validated): dtype-robust types + prefix of lens ------------
__global__ void setup_kernel(const void* __restrict__ tids_raw) {
    const int* s32 = (const int*)tids_raw;
    __shared__ int s[NODES];
    __shared__ int flag64;
    int n = threadIdx.x;
    if (n == 0) flag64 = 1;
    __syncthreads();
    if (n < 256) {
        int lo = s32[2 * n], hi = s32[2 * n + 1];
        if (hi != 0 || (unsigned)lo >= 20u) atomicAnd(&flag64, 0);
    }
    __syncthreads();
    int t = flag64 ? s32[2 * n] : s32[n];
    int l = c_reslen[t];
    d_type[n] = t;
    d_len[n]  = l;
    s[n] = l;
    __syncthreads();
    for (int off = 1; off < NODES; off <<= 1) {
        int v = (n >= off) ? s[n - off] : 0;
        __syncthreads();
        s[n] += v;
        __syncthreads();
    }
    d_gbase[n] = s[n] - l;
}

// ---------------- helpers ----------------
__device__ __forceinline__ uint32_t smem_u32(const void* p) {
    uint32_t a;
    asm("{ .reg .u64 t; cvta.to.shared.u64 t, %1; cvt.u32.u64 %0, t; }"
        : "=r"(a) : "l"(p));
    return a;
}
__device__ __forceinline__ void bf16_split(float f, uint16_t& hb, uint16_t& lb) {
    __nv_bfloat16 h = __float2bfloat16_rn(f);
    float l = f - __bfloat162float(h);
    __nv_bfloat16 g = __float2bfloat16_rn(l);
    hb = __bfloat16_as_ushort(h);
    lb = __bfloat16_as_ushort(g);
}
#define LDSM_X4(r, a) \
    asm volatile("ldmatrix.sync.aligned.m8n8.x4.shared.b16 {%0,%1,%2,%3}, [%4];" \
        : "=r"((r)[0]), "=r"((r)[1]), "=r"((r)[2]), "=r"((r)[3]) : "r"(a))
#define LDSM_X2T(r, a) \
    asm volatile("ldmatrix.sync.aligned.m8n8.x2.trans.shared.b16 {%0,%1}, [%2];" \
        : "=r"((r)[0]), "=r"((r)[1]) : "r"(a))
__device__ __forceinline__ void mma_bf16(float* c, const uint32_t* a, const uint32_t* b) {
    asm volatile(
        "mma.sync.aligned.m16n8k16.row.col.f32.bf16.bf16.f32 "
        "{%0,%1,%2,%3}, {%4,%5,%6,%7}, {%8,%9}, {%0,%1,%2,%3};"
        : "+f"(c[0]), "+f"(c[1]), "+f"(c[2]), "+f"(c[3])
        : "r"(a[0]), "r"(a[1]), "r"(a[2]), "r"(a[3]), "r"(b[0]), "r"(b[1]));
}
#define CP_ASYNC16(dst, src) \
    asm volatile("cp.async.cg.shared.global [%0], [%1], 16;" :: "r"(dst), "l"(src))
#define CP_COMMIT() asm volatile("cp.async.commit_group;" ::: "memory")
#define CP_WAIT0()  asm volatile("cp.async.wait_group 0;" ::: "memory")

// ---------- prep_w: A image per (type, mtile): [64 j][Wh(128B)|Wl(128B)] ------
__global__ void prep_w_kernel(const float* __restrict__ W) {
    __shared__ char Aimg[A_REGION];
    const int t  = blockIdx.x / NTILE_MAX;
    const int mt = blockIdx.x % NTILE_MAX;
    const int tid = threadIdx.x;
    const int jw = tid & 63, ah = tid >> 6;   // 4 amino quarters of 16
    const int jmax = c_reslen[t] * ATOMN;
    const float* Wt = W + (size_t)t * AMINO * RMAXJ;
    {
        int jg = mt * A_ROWS + jw;
        bool val = jg < jmax;
        uint32_t hp[8], lp[8];
#pragma unroll
        for (int q = 0; q < 8; ++q) {
            int a = ah * 16 + 2 * q;
            float w0 = val ? Wt[(size_t)a * RMAXJ + jg] : 0.0f;
            float w1 = val ? Wt[(size_t)(a + 1) * RMAXJ + jg] : 0.0f;
            uint16_t hb0, lb0, hb1, lb1;
            bf16_split(w0, hb0, lb0);
            bf16_split(w1, hb1, lb1);
            hp[q] = (uint32_t)hb0 | ((uint32_t)hb1 << 16);
            lp[q] = (uint32_t)lb0 | ((uint32_t)lb1 << 16);
        }
        char* rowp = Aimg + jw * LDA + ah * 32;
#pragma unroll
        for (int q4 = 0; q4 < 2; ++q4) {
            *reinterpret_cast<uint4*>(rowp + q4 * 16) =
                make_uint4(hp[4*q4], hp[4*q4+1], hp[4*q4+2], hp[4*q4+3]);
            *reinterpret_cast<uint4*>(rowp + 128 + q4 * 16) =
                make_uint4(lp[4*q4], lp[4*q4+1], lp[4*q4+2], lp[4*q4+3]);
        }
    }
    __syncthreads();
    uint4* dst = d_Wprep + (size_t)blockIdx.x * A_V4;
    const uint4* src = (const uint4*)Aimg;
    for (int i = tid; i < A_V4; i += 256) dst[i] = src[i];
}

// ---------- main: prologue X convert + cp.async A, double-buffered ------------
#define SMEM_MAIN (2 * A_REGION + B_REGION)   // 61440

__global__ void __launch_bounds__(256, 3)
lin_amino_kernel(const float* __restrict__ x, float* __restrict__ out, int G) {
    extern __shared__ char smem[];
    const int tid  = threadIdx.x;
    const int warp = tid >> 5;
    const int lane = tid & 31;
    const int bx   = blockIdx.x;
    const int n    = bx >> 1;
    const int half = bx & 1;
    const int t    = d_type[n];
    const int len  = d_len[n];
    const int gb   = d_gbase[n];
    const int ntiles = (len + 1) >> 1;

    const uint32_t Abase = smem_u32(smem);
    const uint32_t Bsm   = Abase + 2 * A_REGION;
    char* Bp = smem + 2 * A_REGION;

    // ---- A tile 0 cp.async (overlaps X convert) ----
    {
        const char* asrc = (const char*)(d_Wprep + (size_t)(t * NTILE_MAX) * A_V4);
        for (int i = tid; i < A_V4; i += 256)
            CP_ASYNC16(Abase + i * 16, asrc + i * 16);
        CP_COMMIT();
    }

    // ---- X convert: direct LDG + split -> B smem (rows a=Xh, 64+a=Xl) ----
    for (int i = tid; i < AMINO * 32; i += 256) {
        int a = i & 63, bl = i >> 6;
        const float* s = x + ((size_t)(half * 32 + bl) * NODES + n) * 192 + a * 3;
        uint16_t h0, l0, h1, l1, h2, l2;
        bf16_split(s[0], h0, l0);
        bf16_split(s[1], h1, l1);
        bf16_split(s[2], h2, l2);
        char* rh = Bp + a * LDB + bl * 6;
        char* rl = rh + 64 * LDB;
        *(uint16_t*)(rh + 0) = h0; *(uint16_t*)(rh + 2) = h1; *(uint16_t*)(rh + 4) = h2;
        *(uint16_t*)(rl + 0) = l0; *(uint16_t*)(rl + 2) = l1; *(uint16_t*)(rl + 4) = l2;
    }

    const int m_block = (warp & 1) * 32;    // warp&1 = residue within tile
    const int n_block = (warp >> 1) * 24;   // 3 n-frags of 8
    const int l15 = lane & 15, lh = lane >> 4;
    const uint32_t aoff_lane = (uint32_t)(m_block + l15) * LDA + lh * 16;
    const uint32_t bbase_lane = Bsm + (uint32_t)l15 * LDB + n_block * 2;

    for (int mt = 0; mt < ntiles; ++mt) {
        CP_WAIT0();
        __syncthreads();
        const uint32_t Acur = Abase + (uint32_t)(mt & 1) * A_REGION;
        const uint32_t aaddr0 = Acur + aoff_lane;
        const uint32_t aaddr1 = aaddr0 + 16 * LDA;

        // ---- mainloop: 12 k-steps = (Wh,Xh)x4, (Wl,Xh)x4, (Wh,Xl)x4 ----
        float acc[2][3][4];
#pragma unroll
        for (int i = 0; i < 2; ++i)
#pragma unroll
            for (int j = 0; j < 3; ++j)
#pragma unroll
                for (int k = 0; k < 4; ++k) acc[i][j][k] = 0.0f;

#pragma unroll
        for (int s = 0; s < 12; ++s) {
            int quad = s >> 2, kk = s & 3;
            int pa = (quad == 1);
            int pb = (quad == 2);
            uint32_t a0[4], a1[4];
            uint32_t aoff = (uint32_t)(pa * 128 + kk * 32);
            LDSM_X4(a0, aaddr0 + aoff);
            LDSM_X4(a1, aaddr1 + aoff);
            uint32_t bk = bbase_lane + (uint32_t)(pb * 64 + kk * 16) * LDB;
#pragma unroll
            for (int nf = 0; nf < 3; ++nf) {
                uint32_t bb[2];
                LDSM_X2T(bb, bk + nf * 16);
                mma_bf16(acc[0][nf], a0, bb);
                mma_bf16(acc[1][nf], a1, bb);
            }
        }

        // ---- prefetch next A tile (overlaps epilogue) ----
        if (mt + 1 < ntiles) {
            const uint32_t Anext = Abase + (uint32_t)((mt + 1) & 1) * A_REGION;
            const char* asrc =
                (const char*)(d_Wprep + (size_t)(t * NTILE_MAX + mt + 1) * A_V4);
            for (int i = tid; i < A_V4; i += 256)
                CP_ASYNC16(Anext + i * 16, asrc + i * 16);
            CP_COMMIT();
        }

        // ---- epilogue: direct STG from D fragments (validated mapping) ----
        {
            int r_idx = mt * 2 + (warp & 1);
            if (r_idx < len) {
                const size_t Gs = (size_t)G * 96;
                float* og = out + (size_t)(gb + r_idx) * 96 + (size_t)(half * 32) * Gs;
                int row0 = lane >> 2, npair = (lane & 3) * 2;
#pragma unroll
                for (int mi = 0; mi < 2; ++mi) {
#pragma unroll
                    for (int nf = 0; nf < 3; ++nf) {
                        int n0 = n_block + nf * 8 + npair;
                        int b0 = n0 / 3, v0 = n0 - 3 * b0;
                        int n1 = n0 + 1;
                        int b1 = n1 / 3, v1 = n1 - 3 * b1;
                        int atomA = mi * 16 + row0;
                        int atomB = atomA + 8;
                        float* p0 = og + (size_t)b0 * Gs;
                        float* p1 = og + (size_t)b1 * Gs;
                        const float* c = acc[mi][nf];
                        p0[atomA * 3 + v0] = c[0];
                        p1[atomA * 3 + v1] = c[1];
                        p0[atomB * 3 + v0] = c[2];
                        p1[atomB * 3 + v1] = c[3];
                    }
                }
            }
        }
    }
}

extern "C" void kernel_launch(void* const* d_in, const int* in_sizes, int n_in,
                              void* d_out, int out_size) {
    const float* x    = (const float*)d_in[0];
    const float* W    = (const float*)d_in[1];
    const void*  tids = d_in[2];
    float*       out  = (float*)d_out;

    int G = in_sizes[3];

    cudaFuncSetAttribute(lin_amino_kernel,
                         cudaFuncAttributeMaxDynamicSharedMemorySize, SMEM_MAIN);

    setup_kernel<<<1, NODES>>>(tids);
    prep_w_kernel<<<20 * NTILE_MAX, 256>>>(W);
    lin_amino_kernel<<<NODES * 2, 256, SMEM_MAIN>>>(x, out, G);
}

// round 10
// speedup vs baseline: 1.7807x; 1.0779x over previous
#include <cuda_runtime.h>
#include <cuda_bf16.h>
#include <cstdint>

// LinAminoToAtom via mma.sync bf16 3-term split.
// R10: setup merged into prep (141-block launch, shfl scan); B frags via
// ldmatrix.x4.trans (2 issues per k-step instead of 3). Mainloop arithmetic
// identical to validated R9 (rel_err 4.44e-6).

#define NODES 512
#define BATCH 64
#define AMINO 64
#define ATOMN 32
#define RMAXJ 416
#define LDA   272              // A smem row stride bytes
#define LDB   208              // B smem row stride bytes
#define A_ROWS 64              // M-tile rows (2 residues)
#define A_REGION (A_ROWS * LDA)   // 17408
#define B_REGION (128 * LDB)      // 26624
#define A_V4  (A_REGION / 16)     // 1088
#define NTILE_MAX 7

__constant__ int c_reslen[20] = {4,10,7,7,5,8,8,3,9,7,7,8,7,10,6,5,6,13,11,6};

__device__ int d_type[NODES];
__device__ int d_len[NODES];
__device__ int d_gbase[NODES];
__device__ uint4 d_Wprep[20 * NTILE_MAX * A_V4];   // per-(type,mtile) A image

// ---------------- helpers ----------------
__device__ __forceinline__ uint32_t smem_u32(const void* p) {
    uint32_t a;
    asm("{ .reg .u64 t; cvta.to.shared.u64 t, %1; cvt.u32.u64 %0, t; }"
        : "=r"(a) : "l"(p));
    return a;
}
__device__ __forceinline__ void bf16_split(float f, uint16_t& hb, uint16_t& lb) {
    __nv_bfloat16 h = __float2bfloat16_rn(f);
    float l = f - __bfloat162float(h);
    __nv_bfloat16 g = __float2bfloat16_rn(l);
    hb = __bfloat16_as_ushort(h);
    lb = __bfloat16_as_ushort(g);
}
#define LDSM_X4(r, a) \
    asm volatile("ldmatrix.sync.aligned.m8n8.x4.shared.b16 {%0,%1,%2,%3}, [%4];" \
        : "=r"((r)[0]), "=r"((r)[1]), "=r"((r)[2]), "=r"((r)[3]) : "r"(a))
#define LDSM_X4T(r, a) \
    asm volatile("ldmatrix.sync.aligned.m8n8.x4.trans.shared.b16 {%0,%1,%2,%3}, [%4];" \
        : "=r"((r)[0]), "=r"((r)[1]), "=r"((r)[2]), "=r"((r)[3]) : "r"(a))
#define LDSM_X2T(r, a) \
    asm volatile("ldmatrix.sync.aligned.m8n8.x2.trans.shared.b16 {%0,%1}, [%2];" \
        : "=r"((r)[0]), "=r"((r)[1]) : "r"(a))
__device__ __forceinline__ void mma_bf16(float* c, const uint32_t* a, const uint32_t* b) {
    asm volatile(
        "mma.sync.aligned.m16n8k16.row.col.f32.bf16.bf16.f32 "
        "{%0,%1,%2,%3}, {%4,%5,%6,%7}, {%8,%9}, {%0,%1,%2,%3};"
        : "+f"(c[0]), "+f"(c[1]), "+f"(c[2]), "+f"(c[3])
        : "r"(a[0]), "r"(a[1]), "r"(a[2]), "r"(a[3]), "r"(b[0]), "r"(b[1]));
}
#define CP_ASYNC16(dst, src) \
    asm volatile("cp.async.cg.shared.global [%0], [%1], 16;" :: "r"(dst), "l"(src))
#define CP_COMMIT() asm volatile("cp.async.commit_group;" ::: "memory")
#define CP_WAIT0()  asm volatile("cp.async.wait_group 0;" ::: "memory")

// ---------- prep: blocks 0..139 build W images; block 140 runs setup scan ----
__global__ void prep_kernel(const float* __restrict__ W,
                            const void* __restrict__ tids_raw) {
    __shared__ char Aimg[A_REGION];
    __shared__ int wsum[16];
    __shared__ int flag64;
    const int bx  = blockIdx.x;
    const int tid = threadIdx.x;

    if (bx == 20 * NTILE_MAX) {
        // ---- setup: dtype-robust type read + shfl prefix scan (validated) ----
        const int* s32 = (const int*)tids_raw;
        int n = tid;                       // 512 threads, one node each
        if (n == 0) flag64 = 1;
        __syncthreads();
        if (n < 256) {
            int lo = s32[2 * n], hi = s32[2 * n + 1];
            if (hi != 0 || (unsigned)lo >= 20u) atomicAnd(&flag64, 0);
        }
        __syncthreads();
        int t = flag64 ? s32[2 * n] : s32[n];
        int l = c_reslen[t];
        d_type[n] = t;
        d_len[n]  = l;
        int lane = n & 31, wid = n >> 5;
        int v = l;
#pragma unroll
        for (int off = 1; off < 32; off <<= 1) {
            int u = __shfl_up_sync(0xffffffffu, v, off);
            if (lane >= off) v += u;
        }
        if (lane == 31) wsum[wid] = v;
        __syncthreads();
        if (wid == 0 && lane < 16) {
            int s = wsum[lane];
#pragma unroll
            for (int off = 1; off < 16; off <<= 1) {
                int u = __shfl_up_sync(0x0000ffffu, s, off);
                if (lane >= off) s += u;
            }
            wsum[lane] = s;
        }
        __syncthreads();
        d_gbase[n] = v - l + (wid > 0 ? wsum[wid - 1] : 0);
        return;
    }

    // ---- W image: [64 j][Wh(128B)|Wl(128B)], 512 threads ----
    const int t  = bx / NTILE_MAX;
    const int mt = bx % NTILE_MAX;
    const int jw = tid & 63, ae = tid >> 6;   // 8 amino-eighths of 8
    const int jmax = c_reslen[t] * ATOMN;
    const float* Wt = W + (size_t)t * AMINO * RMAXJ;
    {
        int jg = mt * A_ROWS + jw;
        bool val = jg < jmax;
        uint32_t hp[4], lp[4];
#pragma unroll
        for (int q = 0; q < 4; ++q) {
            int a = ae * 8 + 2 * q;
            float w0 = val ? Wt[(size_t)a * RMAXJ + jg] : 0.0f;
            float w1 = val ? Wt[(size_t)(a + 1) * RMAXJ + jg] : 0.0f;
            uint16_t hb0, lb0, hb1, lb1;
            bf16_split(w0, hb0, lb0);
            bf16_split(w1, hb1, lb1);
            hp[q] = (uint32_t)hb0 | ((uint32_t)hb1 << 16);
            lp[q] = (uint32_t)lb0 | ((uint32_t)lb1 << 16);
        }
        char* rowp = Aimg + jw * LDA + ae * 16;
        *reinterpret_cast<uint4*>(rowp)       = make_uint4(hp[0], hp[1], hp[2], hp[3]);
        *reinterpret_cast<uint4*>(rowp + 128) = make_uint4(lp[0], lp[1], lp[2], lp[3]);
    }
    __syncthreads();
    uint4* dst = d_Wprep + (size_t)bx * A_V4;
    const uint4* src = (const uint4*)Aimg;
    for (int i = tid; i < A_V4; i += 512) dst[i] = src[i];
}

// ---------- main: prologue X convert + cp.async A, double-buffered ------------
#define SMEM_MAIN (2 * A_REGION + B_REGION)   // 61440

__global__ void __launch_bounds__(256, 3)
lin_amino_kernel(const float* __restrict__ x, float* __restrict__ out, int G) {
    extern __shared__ char smem[];
    const int tid  = threadIdx.x;
    const int warp = tid >> 5;
    const int lane = tid & 31;
    const int bx   = blockIdx.x;
    const int n    = bx >> 1;
    const int half = bx & 1;
    const int t    = d_type[n];
    const int len  = d_len[n];
    const int gb   = d_gbase[n];
    const int ntiles = (len + 1) >> 1;

    const uint32_t Abase = smem_u32(smem);
    const uint32_t Bsm   = Abase + 2 * A_REGION;
    char* Bp = smem + 2 * A_REGION;

    // ---- A tile 0 cp.async (overlaps X convert) ----
    {
        const char* asrc = (const char*)(d_Wprep + (size_t)(t * NTILE_MAX) * A_V4);
        for (int i = tid; i < A_V4; i += 256)
            CP_ASYNC16(Abase + i * 16, asrc + i * 16);
        CP_COMMIT();
    }

    // ---- X convert: direct LDG + split -> B smem (rows a=Xh, 64+a=Xl) ----
    for (int i = tid; i < AMINO * 32; i += 256) {
        int a = i & 63, bl = i >> 6;
        const float* s = x + ((size_t)(half * 32 + bl) * NODES + n) * 192 + a * 3;
        uint16_t h0, l0, h1, l1, h2, l2;
        bf16_split(s[0], h0, l0);
        bf16_split(s[1], h1, l1);
        bf16_split(s[2], h2, l2);
        char* rh = Bp + a * LDB + bl * 6;
        char* rl = rh + 64 * LDB;
        *(uint16_t*)(rh + 0) = h0; *(uint16_t*)(rh + 2) = h1; *(uint16_t*)(rh + 4) = h2;
        *(uint16_t*)(rl + 0) = l0; *(uint16_t*)(rl + 2) = l1; *(uint16_t*)(rl + 4) = l2;
    }

    const int m_block = (warp & 1) * 32;    // warp&1 = residue within tile
    const int n_block = (warp >> 1) * 24;   // 3 n-frags of 8
    const int l15 = lane & 15, lh = lane >> 4;
    const uint32_t aoff_lane = (uint32_t)(m_block + l15) * LDA + lh * 16;
    // x4t: lanes 0-15 -> cols n_block..+8, lanes 16-31 -> +8..+16 (row = lane&15)
    const uint32_t bbase4 = Bsm + (uint32_t)l15 * LDB + (uint32_t)(n_block + lh * 8) * 2;
    const uint32_t bbase2 = Bsm + (uint32_t)l15 * LDB + (uint32_t)(n_block + 16) * 2;

    for (int mt = 0; mt < ntiles; ++mt) {
        CP_WAIT0();
        __syncthreads();
        const uint32_t Acur = Abase + (uint32_t)(mt & 1) * A_REGION;
        const uint32_t aaddr0 = Acur + aoff_lane;
        const uint32_t aaddr1 = aaddr0 + 16 * LDA;

        // ---- mainloop: 12 k-steps = (Wh,Xh)x4, (Wl,Xh)x4, (Wh,Xl)x4 ----
        float acc[2][3][4];
#pragma unroll
        for (int i = 0; i < 2; ++i)
#pragma unroll
            for (int j = 0; j < 3; ++j)
#pragma unroll
                for (int k = 0; k < 4; ++k) acc[i][j][k] = 0.0f;

#pragma unroll
        for (int s = 0; s < 12; ++s) {
            int quad = s >> 2, kk = s & 3;
            int pa = (quad == 1);
            int pb = (quad == 2);
            uint32_t a0[4], a1[4];
            uint32_t aoff = (uint32_t)(pa * 128 + kk * 32);
            LDSM_X4(a0, aaddr0 + aoff);
            LDSM_X4(a1, aaddr1 + aoff);
            uint32_t boff = (uint32_t)(pb * 64 + kk * 16) * LDB;
            uint32_t b01[4], b2[2];
            LDSM_X4T(b01, bbase4 + boff);   // nf0 = {b01[0],b01[1]}, nf1 = {b01[2],b01[3]}
            LDSM_X2T(b2,  bbase2 + boff);   // nf2
            mma_bf16(acc[0][0], a0, b01);
            mma_bf16(acc[1][0], a1, b01);
            mma_bf16(acc[0][1], a0, b01 + 2);
            mma_bf16(acc[1][1], a1, b01 + 2);
            mma_bf16(acc[0][2], a0, b2);
            mma_bf16(acc[1][2], a1, b2);
        }

        // ---- prefetch next A tile (overlaps epilogue) ----
        if (mt + 1 < ntiles) {
            const uint32_t Anext = Abase + (uint32_t)((mt + 1) & 1) * A_REGION;
            const char* asrc =
                (const char*)(d_Wprep + (size_t)(t * NTILE_MAX + mt + 1) * A_V4);
            for (int i = tid; i < A_V4; i += 256)
                CP_ASYNC16(Anext + i * 16, asrc + i * 16);
            CP_COMMIT();
        }

        // ---- epilogue: direct STG from D fragments (validated mapping) ----
        {
            int r_idx = mt * 2 + (warp & 1);
            if (r_idx < len) {
                const size_t Gs = (size_t)G * 96;
                float* og = out + (size_t)(gb + r_idx) * 96 + (size_t)(half * 32) * Gs;
                int row0 = lane >> 2, npair = (lane & 3) * 2;
#pragma unroll
                for (int mi = 0; mi < 2; ++mi) {
#pragma unroll
                    for (int nf = 0; nf < 3; ++nf) {
                        int n0 = n_block + nf * 8 + npair;
                        int b0 = n0 / 3, v0 = n0 - 3 * b0;
                        int n1 = n0 + 1;
                        int b1 = n1 / 3, v1 = n1 - 3 * b1;
                        int atomA = mi * 16 + row0;
                        int atomB = atomA + 8;
                        float* p0 = og + (size_t)b0 * Gs;
                        float* p1 = og + (size_t)b1 * Gs;
                        const float* c = acc[mi][nf];
                        p0[atomA * 3 + v0] = c[0];
                        p1[atomA * 3 + v1] = c[1];
                        p0[atomB * 3 + v0] = c[2];
                        p1[atomB * 3 + v1] = c[3];
                    }
                }
            }
        }
    }
}

extern "C" void kernel_launch(void* const* d_in, const int* in_sizes, int n_in,
                              void* d_out, int out_size) {
    const float* x    = (const float*)d_in[0];
    const float* W    = (const float*)d_in[1];
    const void*  tids = d_in[2];
    float*       out  = (float*)d_out;

    int G = in_sizes[3];

    cudaFuncSetAttribute(lin_amino_kernel,
                         cudaFuncAttributeMaxDynamicSharedMemorySize, SMEM_MAIN);

    prep_kernel<<<20 * NTILE_MAX + 1, 512>>>(W, tids);
    lin_amino_kernel<<<NODES * 2, 256, SMEM_MAIN>>>(x, out, G);
}

// round 11
// speedup vs baseline: 2.0614x; 1.1576x over previous
#include <cuda_runtime.h>
#include <cuda_bf16.h>
#include <cstdint>

// LinAminoToAtom via mma.sync bf16 3-term split.
// R11: k-loop restructured for fragment reuse: per kk load Wh,Wl,Xh,Xl once
// (8 LDSM) and issue all 18 MMAs of the 3 plane-pairs (Wh*Xh, Wl*Xh, Wh*Xl).
// A-prefetch moved ahead of mainloop (full overlap). Other parts = R10.

#define NODES 512
#define BATCH 64
#define AMINO 64
#define ATOMN 32
#define RMAXJ 416
#define LDA   272              // A smem row stride bytes
#define LDB   208              // B smem row stride bytes
#define A_ROWS 64              // M-tile rows (2 residues)
#define A_REGION (A_ROWS * LDA)   // 17408
#define B_REGION (128 * LDB)      // 26624
#define A_V4  (A_REGION / 16)     // 1088
#define NTILE_MAX 7

__constant__ int c_reslen[20] = {4,10,7,7,5,8,8,3,9,7,7,8,7,10,6,5,6,13,11,6};

__device__ int d_type[NODES];
__device__ int d_len[NODES];
__device__ int d_gbase[NODES];
__device__ uint4 d_Wprep[20 * NTILE_MAX * A_V4];   // per-(type,mtile) A image

// ---------------- helpers ----------------
__device__ __forceinline__ uint32_t smem_u32(const void* p) {
    uint32_t a;
    asm("{ .reg .u64 t; cvta.to.shared.u64 t, %1; cvt.u32.u64 %0, t; }"
        : "=r"(a) : "l"(p));
    return a;
}
__device__ __forceinline__ void bf16_split(float f, uint16_t& hb, uint16_t& lb) {
    __nv_bfloat16 h = __float2bfloat16_rn(f);
    float l = f - __bfloat162float(h);
    __nv_bfloat16 g = __float2bfloat16_rn(l);
    hb = __bfloat16_as_ushort(h);
    lb = __bfloat16_as_ushort(g);
}
#define LDSM_X4(r, a) \
    asm volatile("ldmatrix.sync.aligned.m8n8.x4.shared.b16 {%0,%1,%2,%3}, [%4];" \
        : "=r"((r)[0]), "=r"((r)[1]), "=r"((r)[2]), "=r"((r)[3]) : "r"(a))
#define LDSM_X4T(r, a) \
    asm volatile("ldmatrix.sync.aligned.m8n8.x4.trans.shared.b16 {%0,%1,%2,%3}, [%4];" \
        : "=r"((r)[0]), "=r"((r)[1]), "=r"((r)[2]), "=r"((r)[3]) : "r"(a))
#define LDSM_X2T(r, a) \
    asm volatile("ldmatrix.sync.aligned.m8n8.x2.trans.shared.b16 {%0,%1}, [%2];" \
        : "=r"((r)[0]), "=r"((r)[1]) : "r"(a))
__device__ __forceinline__ void mma_bf16(float* c, const uint32_t* a, const uint32_t* b) {
    asm volatile(
        "mma.sync.aligned.m16n8k16.row.col.f32.bf16.bf16.f32 "
        "{%0,%1,%2,%3}, {%4,%5,%6,%7}, {%8,%9}, {%0,%1,%2,%3};"
        : "+f"(c[0]), "+f"(c[1]), "+f"(c[2]), "+f"(c[3])
        : "r"(a[0]), "r"(a[1]), "r"(a[2]), "r"(a[3]), "r"(b[0]), "r"(b[1]));
}
#define CP_ASYNC16(dst, src) \
    asm volatile("cp.async.cg.shared.global [%0], [%1], 16;" :: "r"(dst), "l"(src))
#define CP_COMMIT() asm volatile("cp.async.commit_group;" ::: "memory")
#define CP_WAIT0()  asm volatile("cp.async.wait_group 0;" ::: "memory")

// ---------- prep: blocks 0..139 build W images; block 140 runs setup scan ----
__global__ void prep_kernel(const float* __restrict__ W,
                            const void* __restrict__ tids_raw) {
    __shared__ char Aimg[A_REGION];
    __shared__ int wsum[16];
    __shared__ int flag64;
    const int bx  = blockIdx.x;
    const int tid = threadIdx.x;

    if (bx == 20 * NTILE_MAX) {
        // ---- setup: dtype-robust type read + shfl prefix scan (validated) ----
        const int* s32 = (const int*)tids_raw;
        int n = tid;
        if (n == 0) flag64 = 1;
        __syncthreads();
        if (n < 256) {
            int lo = s32[2 * n], hi = s32[2 * n + 1];
            if (hi != 0 || (unsigned)lo >= 20u) atomicAnd(&flag64, 0);
        }
        __syncthreads();
        int t = flag64 ? s32[2 * n] : s32[n];
        int l = c_reslen[t];
        d_type[n] = t;
        d_len[n]  = l;
        int lane = n & 31, wid = n >> 5;
        int v = l;
#pragma unroll
        for (int off = 1; off < 32; off <<= 1) {
            int u = __shfl_up_sync(0xffffffffu, v, off);
            if (lane >= off) v += u;
        }
        if (lane == 31) wsum[wid] = v;
        __syncthreads();
        if (wid == 0 && lane < 16) {
            int s = wsum[lane];
#pragma unroll
            for (int off = 1; off < 16; off <<= 1) {
                int u = __shfl_up_sync(0x0000ffffu, s, off);
                if (lane >= off) s += u;
            }
            wsum[lane] = s;
        }
        __syncthreads();
        d_gbase[n] = v - l + (wid > 0 ? wsum[wid - 1] : 0);
        return;
    }

    // ---- W image: [64 j][Wh(128B)|Wl(128B)], 512 threads ----
    const int t  = bx / NTILE_MAX;
    const int mt = bx % NTILE_MAX;
    const int jw = tid & 63, ae = tid >> 6;
    const int jmax = c_reslen[t] * ATOMN;
    const float* Wt = W + (size_t)t * AMINO * RMAXJ;
    {
        int jg = mt * A_ROWS + jw;
        bool val = jg < jmax;
        uint32_t hp[4], lp[4];
#pragma unroll
        for (int q = 0; q < 4; ++q) {
            int a = ae * 8 + 2 * q;
            float w0 = val ? Wt[(size_t)a * RMAXJ + jg] : 0.0f;
            float w1 = val ? Wt[(size_t)(a + 1) * RMAXJ + jg] : 0.0f;
            uint16_t hb0, lb0, hb1, lb1;
            bf16_split(w0, hb0, lb0);
            bf16_split(w1, hb1, lb1);
            hp[q] = (uint32_t)hb0 | ((uint32_t)hb1 << 16);
            lp[q] = (uint32_t)lb0 | ((uint32_t)lb1 << 16);
        }
        char* rowp = Aimg + jw * LDA + ae * 16;
        *reinterpret_cast<uint4*>(rowp)       = make_uint4(hp[0], hp[1], hp[2], hp[3]);
        *reinterpret_cast<uint4*>(rowp + 128) = make_uint4(lp[0], lp[1], lp[2], lp[3]);
    }
    __syncthreads();
    uint4* dst = d_Wprep + (size_t)bx * A_V4;
    const uint4* src = (const uint4*)Aimg;
    for (int i = tid; i < A_V4; i += 512) dst[i] = src[i];
}

// ---------- main ----------
#define SMEM_MAIN (2 * A_REGION + B_REGION)   // 61440

__global__ void __launch_bounds__(256, 3)
lin_amino_kernel(const float* __restrict__ x, float* __restrict__ out, int G) {
    extern __shared__ char smem[];
    const int tid  = threadIdx.x;
    const int warp = tid >> 5;
    const int lane = tid & 31;
    const int bx   = blockIdx.x;
    const int n    = bx >> 1;
    const int half = bx & 1;
    const int t    = d_type[n];
    const int len  = d_len[n];
    const int gb   = d_gbase[n];
    const int ntiles = (len + 1) >> 1;

    const uint32_t Abase = smem_u32(smem);
    const uint32_t Bsm   = Abase + 2 * A_REGION;
    char* Bp = smem + 2 * A_REGION;

    // ---- A tile 0 cp.async (overlaps X convert) ----
    {
        const char* asrc = (const char*)(d_Wprep + (size_t)(t * NTILE_MAX) * A_V4);
        for (int i = tid; i < A_V4; i += 256)
            CP_ASYNC16(Abase + i * 16, asrc + i * 16);
        CP_COMMIT();
    }

    // ---- X convert: direct LDG + split -> B smem (rows a=Xh, 64+a=Xl) ----
    for (int i = tid; i < AMINO * 32; i += 256) {
        int a = i & 63, bl = i >> 6;
        const float* s = x + ((size_t)(half * 32 + bl) * NODES + n) * 192 + a * 3;
        uint16_t h0, l0, h1, l1, h2, l2;
        bf16_split(s[0], h0, l0);
        bf16_split(s[1], h1, l1);
        bf16_split(s[2], h2, l2);
        char* rh = Bp + a * LDB + bl * 6;
        char* rl = rh + 64 * LDB;
        *(uint16_t*)(rh + 0) = h0; *(uint16_t*)(rh + 2) = h1; *(uint16_t*)(rh + 4) = h2;
        *(uint16_t*)(rl + 0) = l0; *(uint16_t*)(rl + 2) = l1; *(uint16_t*)(rl + 4) = l2;
    }

    const int m_block = (warp & 1) * 32;    // warp&1 = residue within tile
    const int n_block = (warp >> 1) * 24;   // 3 n-frags of 8
    const int l15 = lane & 15, lh = lane >> 4;
    const uint32_t aoff_lane = (uint32_t)(m_block + l15) * LDA + lh * 16;
    const uint32_t bbase4 = Bsm + (uint32_t)l15 * LDB + (uint32_t)(n_block + lh * 8) * 2;
    const uint32_t bbase2 = Bsm + (uint32_t)l15 * LDB + (uint32_t)(n_block + 16) * 2;

    for (int mt = 0; mt < ntiles; ++mt) {
        CP_WAIT0();
        __syncthreads();

        // ---- prefetch next A tile NOW: overlaps whole mainloop ----
        // buffer (mt+1)&1 was consumed in tile mt-1; free after the barrier.
        if (mt + 1 < ntiles) {
            const uint32_t Anext = Abase + (uint32_t)((mt + 1) & 1) * A_REGION;
            const char* asrc =
                (const char*)(d_Wprep + (size_t)(t * NTILE_MAX + mt + 1) * A_V4);
            for (int i = tid; i < A_V4; i += 256)
                CP_ASYNC16(Anext + i * 16, asrc + i * 16);
            CP_COMMIT();
        }

        const uint32_t Acur = Abase + (uint32_t)(mt & 1) * A_REGION;
        const uint32_t aaddr0 = Acur + aoff_lane;
        const uint32_t aaddr1 = aaddr0 + 16 * LDA;

        // ---- mainloop: 4 kk-steps; per kk load Wh,Wl,Xh,Xl once, 18 MMAs ----
        float acc[2][3][4];
#pragma unroll
        for (int i = 0; i < 2; ++i)
#pragma unroll
            for (int j = 0; j < 3; ++j)
#pragma unroll
                for (int k = 0; k < 4; ++k) acc[i][j][k] = 0.0f;

#pragma unroll
        for (int kk = 0; kk < 4; ++kk) {
            const uint32_t koff = (uint32_t)kk * 32;
            const uint32_t bo   = (uint32_t)(kk * 16) * LDB;
            uint32_t aWh0[4], aWh1[4], aWl0[4], aWl1[4];
            LDSM_X4(aWh0, aaddr0 + koff);
            LDSM_X4(aWh1, aaddr1 + koff);
            LDSM_X4(aWl0, aaddr0 + 128 + koff);
            LDSM_X4(aWl1, aaddr1 + 128 + koff);
            uint32_t bh01[4], bh2[2], bl01[4], bl2[2];
            LDSM_X4T(bh01, bbase4 + bo);
            LDSM_X2T(bh2,  bbase2 + bo);
            LDSM_X4T(bl01, bbase4 + 64 * LDB + bo);
            LDSM_X2T(bl2,  bbase2 + 64 * LDB + bo);
            // Wh * Xh
            mma_bf16(acc[0][0], aWh0, bh01);     mma_bf16(acc[1][0], aWh1, bh01);
            mma_bf16(acc[0][1], aWh0, bh01 + 2); mma_bf16(acc[1][1], aWh1, bh01 + 2);
            mma_bf16(acc[0][2], aWh0, bh2);      mma_bf16(acc[1][2], aWh1, bh2);
            // Wl * Xh
            mma_bf16(acc[0][0], aWl0, bh01);     mma_bf16(acc[1][0], aWl1, bh01);
            mma_bf16(acc[0][1], aWl0, bh01 + 2); mma_bf16(acc[1][1], aWl1, bh01 + 2);
            mma_bf16(acc[0][2], aWl0, bh2);      mma_bf16(acc[1][2], aWl1, bh2);
            // Wh * Xl
            mma_bf16(acc[0][0], aWh0, bl01);     mma_bf16(acc[1][0], aWh1, bl01);
            mma_bf16(acc[0][1], aWh0, bl01 + 2); mma_bf16(acc[1][1], aWh1, bl01 + 2);
            mma_bf16(acc[0][2], aWh0, bl2);      mma_bf16(acc[1][2], aWh1, bl2);
        }

        // ---- epilogue: direct STG from D fragments (validated mapping) ----
        {
            int r_idx = mt * 2 + (warp & 1);
            if (r_idx < len) {
                const size_t Gs = (size_t)G * 96;
                float* og = out + (size_t)(gb + r_idx) * 96 + (size_t)(half * 32) * Gs;
                int row0 = lane >> 2, npair = (lane & 3) * 2;
#pragma unroll
                for (int mi = 0; mi < 2; ++mi) {
#pragma unroll
                    for (int nf = 0; nf < 3; ++nf) {
                        int n0 = n_block + nf * 8 + npair;
                        int b0 = n0 / 3, v0 = n0 - 3 * b0;
                        int n1 = n0 + 1;
                        int b1 = n1 / 3, v1 = n1 - 3 * b1;
                        int atomA = mi * 16 + row0;
                        int atomB = atomA + 8;
                        float* p0 = og + (size_t)b0 * Gs;
                        float* p1 = og + (size_t)b1 * Gs;
                        const float* c = acc[mi][nf];
                        p0[atomA * 3 + v0] = c[0];
                        p1[atomA * 3 + v1] = c[1];
                        p0[atomB * 3 + v0] = c[2];
                        p1[atomB * 3 + v1] = c[3];
                    }
                }
            }
        }
    }
}

extern "C" void kernel_launch(void* const* d_in, const int* in_sizes, int n_in,
                              void* d_out, int out_size) {
    const float* x    = (const float*)d_in[0];
    const float* W    = (const float*)d_in[1];
    const void*  tids = d_in[2];
    float*       out  = (float*)d_out;

    int G = in_sizes[3];

    cudaFuncSetAttribute(lin_amino_kernel,
                         cudaFuncAttributeMaxDynamicSharedMemorySize, SMEM_MAIN);

    prep_kernel<<<20 * NTILE_MAX + 1, 512>>>(W, tids);
    lin_amino_kernel<<<NODES * 2, 256, SMEM_MAIN>>>(x, out, G);
}